// round 15
// baseline (speedup 1.0000x reference)
#include <cuda_runtime.h>
#include <cstdint>

#define N_NODES 8192
#define K_IN    512
#define F_OUT   64
#define NEG_SLOPE 0.01f
#define SEG     128     // per-warp index segment (max per-warp nonzeros ~40 for p=0.01)

// packed fp32x2 FMA (sm_100+; ptxas never auto-fuses — PTX only)
#define PACK_F32X2(d, lo, hi) \
    asm("mov.b64 %0, {%1, %2};" : "=l"(d) : "f"(lo), "f"(hi))
#define UNPACK_F32X2(lo, hi, v) \
    asm("mov.b64 {%0, %1}, %2;" : "=f"(lo), "=f"(hi) : "l"(v))
#define FMA_F32X2(acc, a, b) \
    asm("fma.rn.f32x2 %0, %1, %2, %0;" : "+l"(acc) : "l"(a), "l"(b))

// ---------------- scratch ----------------
__device__ __align__(16) float g_Z[N_NODES * F_OUT];
__device__ float g_zi[N_NODES];
__device__ float g_zj[N_NODES];
__device__ float g_S[F_OUT];

// ---------------- kernel 1: fused GEMM + row-dots + col-sums (f32x2) ---------------
// tile: 64 rows x 64 cols, 256 threads, 4x4 micro-tile via fma.rn.f32x2, grid = 128
__global__ __launch_bounds__(256) void gemm_fused_kernel(
    const float* __restrict__ X, const float* __restrict__ W,
    const float* __restrict__ bias,
    const float* __restrict__ a1, const float* __restrict__ a2)
{
    cudaTriggerProgrammaticLaunchCompletion();

    __shared__ float At[64][68];   // [k][row]
    __shared__ float Bs[64][68];   // [k][out]
    __shared__ float cs[F_OUT];

    const int tid  = threadIdx.x;
    const int tx   = tid & 15;
    const int ty   = tid >> 4;
    const int row0 = blockIdx.x * 64;

    unsigned long long acc01[4] = {0ull, 0ull, 0ull, 0ull};
    unsigned long long acc23[4] = {0ull, 0ull, 0ull, 0ull};

    for (int k0 = 0; k0 < K_IN; k0 += 64) {
        #pragma unroll
        for (int q = 0; q < 4; q++) {
            int idx = tid + 256 * q;
            int r   = idx >> 4;
            int kk4 = (idx & 15) << 2;
            float4 xv = *(const float4*)&X[(size_t)(row0 + r) * K_IN + k0 + kk4];
            At[kk4 + 0][r] = xv.x;
            At[kk4 + 1][r] = xv.y;
            At[kk4 + 2][r] = xv.z;
            At[kk4 + 3][r] = xv.w;
            float4 wv = *(const float4*)&W[(size_t)r * K_IN + k0 + kk4];
            Bs[kk4 + 0][r] = wv.x;
            Bs[kk4 + 1][r] = wv.y;
            Bs[kk4 + 2][r] = wv.z;
            Bs[kk4 + 3][r] = wv.w;
        }
        __syncthreads();

        #pragma unroll 16
        for (int kk = 0; kk < 64; kk++) {
            float4 av = *(const float4*)&At[kk][ty * 4];
            float4 bv = *(const float4*)&Bs[kk][tx * 4];
            unsigned long long b01, b23;
            PACK_F32X2(b01, bv.x, bv.y);
            PACK_F32X2(b23, bv.z, bv.w);
            unsigned long long aa;
            PACK_F32X2(aa, av.x, av.x);
            FMA_F32X2(acc01[0], aa, b01);
            FMA_F32X2(acc23[0], aa, b23);
            PACK_F32X2(aa, av.y, av.y);
            FMA_F32X2(acc01[1], aa, b01);
            FMA_F32X2(acc23[1], aa, b23);
            PACK_F32X2(aa, av.z, av.z);
            FMA_F32X2(acc01[2], aa, b01);
            FMA_F32X2(acc23[2], aa, b23);
            PACK_F32X2(aa, av.w, av.w);
            FMA_F32X2(acc01[3], aa, b01);
            FMA_F32X2(acc23[3], aa, b23);
        }
        __syncthreads();
    }

    float acc[4][4];
    #pragma unroll
    for (int u = 0; u < 4; u++) {
        UNPACK_F32X2(acc[u][0], acc[u][1], acc01[u]);
        UNPACK_F32X2(acc[u][2], acc[u][3], acc23[u]);
    }

    #pragma unroll
    for (int v = 0; v < 4; v++) {
        float bb = __ldg(&bias[tx * 4 + v]);
        #pragma unroll
        for (int u = 0; u < 4; u++) acc[u][v] += bb;
    }

    #pragma unroll
    for (int u = 0; u < 4; u++) {
        float4 zo = make_float4(acc[u][0], acc[u][1], acc[u][2], acc[u][3]);
        *(float4*)&g_Z[(size_t)(row0 + ty * 4 + u) * F_OUT + tx * 4] = zo;
    }

    #pragma unroll
    for (int u = 0; u < 4; u++) {
        float s1 = 0.f, s2 = 0.f;
        #pragma unroll
        for (int v = 0; v < 4; v++) {
            float a1s = __ldg(&a1[tx * 4 + v]);
            float a2s = __ldg(&a2[tx * 4 + v]);
            s1 += a1s * acc[u][v];
            s2 += a2s * acc[u][v];
        }
        #pragma unroll
        for (int off = 8; off > 0; off >>= 1) {
            s1 += __shfl_down_sync(0xFFFFFFFFu, s1, off, 16);
            s2 += __shfl_down_sync(0xFFFFFFFFu, s2, off, 16);
        }
        if (tx == 0) {
            g_zi[row0 + ty * 4 + u] = s1;
            g_zj[row0 + ty * 4 + u] = s2;
        }
    }

    if (tid < F_OUT) cs[tid] = 0.0f;
    __syncthreads();
    #pragma unroll
    for (int v = 0; v < 4; v++)
        atomicAdd(&cs[tx * 4 + v], acc[0][v] + acc[1][v] + acc[2][v] + acc[3][v]);
    __syncthreads();
    if (tid < F_OUT) atomicAdd(&g_S[tid], cs[tid]);
}

// ---------------- kernel 2: warp-segmented scan + gather + closed form -------------
// one block per row; 256 threads = 8 warps; NO shared atomics in the hot loop
__global__ __launch_bounds__(256) void attn_kernel(
    const float* __restrict__ adj, float* __restrict__ out)
{
    __shared__ int   s_idx[8][SEG];
    __shared__ int   s_wcnt[8];
    __shared__ int   s_wdiag[8];
    __shared__ float s_red[4][F_OUT];

    const int i    = blockIdx.x;
    const int tid  = threadIdx.x;
    const int w    = tid >> 5;
    const int lane = tid & 31;
    const unsigned lt = (1u << lane) - 1u;

    // phase 1: scan — each warp compacts into its private segment, count in register
    const float4* row = (const float4*)(adj + (size_t)i * N_NODES);
    int* seg = &s_idx[w][0];
    int wcnt = 0;
    int dgw  = 0;
    #pragma unroll
    for (int q = 0; q < 8; q++) {
        int f4 = tid + q * 256;
        float4 v = __ldcs(&row[f4]);
        unsigned m0 = __ballot_sync(0xFFFFFFFFu, v.x != 0.0f);
        unsigned m1 = __ballot_sync(0xFFFFFFFFu, v.y != 0.0f);
        unsigned m2 = __ballot_sync(0xFFFFFFFFu, v.z != 0.0f);
        unsigned m3 = __ballot_sync(0xFFFFFFFFu, v.w != 0.0f);
        int j = f4 << 2;
        int base = wcnt;
        if (v.x != 0.0f) { seg[base + __popc(m0 & lt)] = j;     if (j     == i) dgw = 1; }
        base += __popc(m0);
        if (v.y != 0.0f) { seg[base + __popc(m1 & lt)] = j + 1; if (j + 1 == i) dgw = 1; }
        base += __popc(m1);
        if (v.z != 0.0f) { seg[base + __popc(m2 & lt)] = j + 2; if (j + 2 == i) dgw = 1; }
        base += __popc(m2);
        if (v.w != 0.0f) { seg[base + __popc(m3 & lt)] = j + 3; if (j + 3 == i) dgw = 1; }
        wcnt = base + __popc(m3);
    }
    unsigned danyb = __ballot_sync(0xFFFFFFFFu, dgw != 0);
    if (lane == 0) {
        s_wcnt[w]  = wcnt;
        s_wdiag[w] = (danyb != 0u);
    }
    __syncthreads();

    // wait for the GEMM grid (Z, zi, zj, S) — scan above overlapped with it (PDL)
    cudaGridDependencySynchronize();

    // phase 2: R_full[o] = sum over all 8 segments of z[idx][o]
    const int o = tid & 63;
    const int g = tid >> 6;
    float acc = 0.0f;
    #pragma unroll
    for (int s = 0; s < 8; s++) {
        const int c = s_wcnt[s];
        const int* sg = &s_idx[s][0];
        for (int p = g; p < c; p += 4)
            acc += __ldg(&g_Z[(size_t)sg[p] * F_OUT + o]);
    }
    s_red[g][o] = acc;
    __syncthreads();

    // phase 3: closed-form softmax aggregation + residual + relu
    if (tid < F_OUT) {
        int cnt = 0, dg = 0;
        #pragma unroll
        for (int s = 0; s < 8; s++) { cnt += s_wcnt[s]; dg |= s_wdiag[s]; }

        float Rfull = s_red[0][o] + s_red[1][o] + s_red[2][o] + s_red[3][o];
        float zio   = g_Z[(size_t)i * F_OUT + o];
        float Roff  = Rfull - (dg ? zio : 0.0f);
        int   koff  = cnt - dg;

        float c  = g_zi[i];
        float lc = c > 0.0f ? c : NEG_SLOPE * c;
        float e1 = expf(lc);
        float wd = 1.0f;
        if (dg) {
            float t = c + g_zj[i];
            t = t > 0.0f ? t : NEG_SLOPE * t;
            wd = expf(t);
        }
        float Zden  = (float)koff * e1 + wd + (float)(N_NODES - 1 - koff);
        float numer = (e1 - 1.0f) * Roff + (wd - 1.0f) * zio + g_S[o];
        float h = zio - numer / Zden;
        out[(size_t)i * F_OUT + o] = h > 0.0f ? h : 0.0f;
    }
}

// ---------------- launch ----------------
extern "C" void kernel_launch(void* const* d_in, const int* in_sizes, int n_in,
                              void* d_out, int out_size)
{
    const float* X    = (const float*)d_in[0];
    const float* adj  = (const float*)d_in[1];
    // d_in[2] = eye_matrix: identity by construction, never read
    const float* W    = (const float*)d_in[3];
    const float* bias = (const float*)d_in[4];
    const float* a1   = (const float*)d_in[5];
    const float* a2   = (const float*)d_in[6];
    float* out        = (float*)d_out;

    void* sPtr = nullptr;
    cudaGetSymbolAddress(&sPtr, g_S);
    cudaMemsetAsync(sPtr, 0, F_OUT * sizeof(float));

    // primary: GEMM — fires PDL trigger at block start
    gemm_fused_kernel<<<N_NODES / 64, 256>>>(X, W, bias, a1, a2);

    // secondary: attn with programmatic stream serialization (PDL)
    cudaLaunchConfig_t cfg = {};
    cfg.gridDim  = dim3(N_NODES, 1, 1);
    cfg.blockDim = dim3(256, 1, 1);
    cfg.dynamicSmemBytes = 0;
    cfg.stream = 0;
    cudaLaunchAttribute attrs[1];
    attrs[0].id = cudaLaunchAttributeProgrammaticStreamSerialization;
    attrs[0].val.programmaticStreamSerializationAllowed = 1;
    cfg.attrs = attrs;
    cfg.numAttrs = 1;
    cudaLaunchKernelEx(&cfg, attn_kernel, adj, out);
}

// round 16
// speedup vs baseline: 1.0766x; 1.0766x over previous
#include <cuda_runtime.h>
#include <cstdint>

#define N_NODES 8192
#define K_IN    512
#define F_OUT   64
#define NEG_SLOPE 0.01f

// packed fp32x2 FMA (sm_100+; ptxas never auto-fuses — PTX only)
#define PACK_F32X2(d, lo, hi) \
    asm("mov.b64 %0, {%1, %2};" : "=l"(d) : "f"(lo), "f"(hi))
#define UNPACK_F32X2(lo, hi, v) \
    asm("mov.b64 {%0, %1}, %2;" : "=f"(lo), "=f"(hi) : "l"(v))
#define FMA_F32X2(acc, a, b) \
    asm("fma.rn.f32x2 %0, %1, %2, %0;" : "+l"(acc) : "l"(a), "l"(b))

// ---------------- scratch ----------------
__device__ __align__(16) float g_Z[N_NODES * F_OUT];
__device__ float g_zi[N_NODES];
__device__ float g_zj[N_NODES];
__device__ float g_S[F_OUT];

// ---------------- kernel 1: fused GEMM + row-dots + col-sums (f32x2) ---------------
// tile: 64 rows x 64 cols, 256 threads, 4x4 micro-tile via fma.rn.f32x2, grid = 128
__global__ __launch_bounds__(256) void gemm_fused_kernel(
    const float* __restrict__ X, const float* __restrict__ W,
    const float* __restrict__ bias,
    const float* __restrict__ a1, const float* __restrict__ a2)
{
    cudaTriggerProgrammaticLaunchCompletion();

    __shared__ float At[64][68];   // [k][row]
    __shared__ float Bs[64][68];   // [k][out]
    __shared__ float cs[F_OUT];

    const int tid  = threadIdx.x;
    const int tx   = tid & 15;
    const int ty   = tid >> 4;
    const int row0 = blockIdx.x * 64;

    unsigned long long acc01[4] = {0ull, 0ull, 0ull, 0ull};
    unsigned long long acc23[4] = {0ull, 0ull, 0ull, 0ull};

    for (int k0 = 0; k0 < K_IN; k0 += 64) {
        #pragma unroll
        for (int q = 0; q < 4; q++) {
            int idx = tid + 256 * q;
            int r   = idx >> 4;
            int kk4 = (idx & 15) << 2;
            float4 xv = *(const float4*)&X[(size_t)(row0 + r) * K_IN + k0 + kk4];
            At[kk4 + 0][r] = xv.x;
            At[kk4 + 1][r] = xv.y;
            At[kk4 + 2][r] = xv.z;
            At[kk4 + 3][r] = xv.w;
            float4 wv = *(const float4*)&W[(size_t)r * K_IN + k0 + kk4];
            Bs[kk4 + 0][r] = wv.x;
            Bs[kk4 + 1][r] = wv.y;
            Bs[kk4 + 2][r] = wv.z;
            Bs[kk4 + 3][r] = wv.w;
        }
        __syncthreads();

        #pragma unroll 16
        for (int kk = 0; kk < 64; kk++) {
            float4 av = *(const float4*)&At[kk][ty * 4];
            float4 bv = *(const float4*)&Bs[kk][tx * 4];
            unsigned long long b01, b23;
            PACK_F32X2(b01, bv.x, bv.y);
            PACK_F32X2(b23, bv.z, bv.w);
            unsigned long long aa;
            PACK_F32X2(aa, av.x, av.x);
            FMA_F32X2(acc01[0], aa, b01);
            FMA_F32X2(acc23[0], aa, b23);
            PACK_F32X2(aa, av.y, av.y);
            FMA_F32X2(acc01[1], aa, b01);
            FMA_F32X2(acc23[1], aa, b23);
            PACK_F32X2(aa, av.z, av.z);
            FMA_F32X2(acc01[2], aa, b01);
            FMA_F32X2(acc23[2], aa, b23);
            PACK_F32X2(aa, av.w, av.w);
            FMA_F32X2(acc01[3], aa, b01);
            FMA_F32X2(acc23[3], aa, b23);
        }
        __syncthreads();
    }

    float acc[4][4];
    #pragma unroll
    for (int u = 0; u < 4; u++) {
        UNPACK_F32X2(acc[u][0], acc[u][1], acc01[u]);
        UNPACK_F32X2(acc[u][2], acc[u][3], acc23[u]);
    }

    #pragma unroll
    for (int v = 0; v < 4; v++) {
        float bb = __ldg(&bias[tx * 4 + v]);
        #pragma unroll
        for (int u = 0; u < 4; u++) acc[u][v] += bb;
    }

    #pragma unroll
    for (int u = 0; u < 4; u++) {
        float4 zo = make_float4(acc[u][0], acc[u][1], acc[u][2], acc[u][3]);
        *(float4*)&g_Z[(size_t)(row0 + ty * 4 + u) * F_OUT + tx * 4] = zo;
    }

    #pragma unroll
    for (int u = 0; u < 4; u++) {
        float s1 = 0.f, s2 = 0.f;
        #pragma unroll
        for (int v = 0; v < 4; v++) {
            float a1s = __ldg(&a1[tx * 4 + v]);
            float a2s = __ldg(&a2[tx * 4 + v]);
            s1 += a1s * acc[u][v];
            s2 += a2s * acc[u][v];
        }
        #pragma unroll
        for (int off = 8; off > 0; off >>= 1) {
            s1 += __shfl_down_sync(0xFFFFFFFFu, s1, off, 16);
            s2 += __shfl_down_sync(0xFFFFFFFFu, s2, off, 16);
        }
        if (tx == 0) {
            g_zi[row0 + ty * 4 + u] = s1;
            g_zj[row0 + ty * 4 + u] = s2;
        }
    }

    if (tid < F_OUT) cs[tid] = 0.0f;
    __syncthreads();
    #pragma unroll
    for (int v = 0; v < 4; v++)
        atomicAdd(&cs[tx * 4 + v], acc[0][v] + acc[1][v] + acc[2][v] + acc[3][v]);
    __syncthreads();
    if (tid < F_OUT) atomicAdd(&g_S[tid], cs[tid]);
}

// ---------------- kernel 2: stream adj + gather + closed-form softmax --------------
// one block per row; 256 threads — verbatim round-12 structure (measured best)
__global__ __launch_bounds__(256) void attn_kernel(
    const float* __restrict__ adj, float* __restrict__ out)
{
    __shared__ int   s_idx[2048];
    __shared__ int   s_cnt;
    __shared__ int   s_diag;
    __shared__ float s_red[4][F_OUT];

    const int i   = blockIdx.x;
    const int tid = threadIdx.x;

    if (tid == 0) { s_cnt = 0; s_diag = 0; }
    __syncthreads();

    // phase 1: scan row i of adj (8192 floats = 2048 float4), streaming hint.
    const float4* row = (const float4*)(adj + (size_t)i * N_NODES);
    #pragma unroll
    for (int q = 0; q < 8; q++) {
        int f4 = tid + q * 256;
        float4 v = __ldcs(&row[f4]);
        int j = f4 << 2;
        if (v.x != 0.0f) { int p = atomicAdd(&s_cnt, 1); s_idx[p] = j;     if (j     == i) s_diag = 1; }
        if (v.y != 0.0f) { int p = atomicAdd(&s_cnt, 1); s_idx[p] = j + 1; if (j + 1 == i) s_diag = 1; }
        if (v.z != 0.0f) { int p = atomicAdd(&s_cnt, 1); s_idx[p] = j + 2; if (j + 2 == i) s_diag = 1; }
        if (v.w != 0.0f) { int p = atomicAdd(&s_cnt, 1); s_idx[p] = j + 3; if (j + 3 == i) s_diag = 1; }
    }
    __syncthreads();

    // wait for the GEMM grid (Z, zi, zj, S) — scan above overlapped with it (PDL)
    cudaGridDependencySynchronize();

    const int cnt = s_cnt;
    const int dg  = s_diag;

    // phase 2: R_full[o] = sum over neighbor list of z[j][o]
    const int o = tid & 63;
    const int g = tid >> 6;
    float acc = 0.0f;
    for (int p = g; p < cnt; p += 4)
        acc += __ldg(&g_Z[(size_t)s_idx[p] * F_OUT + o]);
    s_red[g][o] = acc;
    __syncthreads();

    // phase 3: closed-form softmax-weighted aggregation + residual + relu
    if (tid < F_OUT) {
        float Rfull = s_red[0][o] + s_red[1][o] + s_red[2][o] + s_red[3][o];
        float zio   = g_Z[(size_t)i * F_OUT + o];
        float Roff  = Rfull - (dg ? zio : 0.0f);
        int   koff  = cnt - dg;

        float c  = g_zi[i];
        float lc = c > 0.0f ? c : NEG_SLOPE * c;
        float e1 = expf(lc);
        float wd = 1.0f;
        if (dg) {
            float t = c + g_zj[i];
            t = t > 0.0f ? t : NEG_SLOPE * t;
            wd = expf(t);
        }
        float Zden  = (float)koff * e1 + wd + (float)(N_NODES - 1 - koff);
        float numer = (e1 - 1.0f) * Roff + (wd - 1.0f) * zio + g_S[o];
        float h = zio - numer / Zden;
        out[(size_t)i * F_OUT + o] = h > 0.0f ? h : 0.0f;
    }
}

// ---------------- launch ----------------
extern "C" void kernel_launch(void* const* d_in, const int* in_sizes, int n_in,
                              void* d_out, int out_size)
{
    const float* X    = (const float*)d_in[0];
    const float* adj  = (const float*)d_in[1];
    // d_in[2] = eye_matrix: identity by construction, never read
    const float* W    = (const float*)d_in[3];
    const float* bias = (const float*)d_in[4];
    const float* a1   = (const float*)d_in[5];
    const float* a2   = (const float*)d_in[6];
    float* out        = (float*)d_out;

    void* sPtr = nullptr;
    cudaGetSymbolAddress(&sPtr, g_S);
    cudaMemsetAsync(sPtr, 0, F_OUT * sizeof(float));

    // primary: GEMM — fires PDL trigger at block start
    gemm_fused_kernel<<<N_NODES / 64, 256>>>(X, W, bias, a1, a2);

    // secondary: attn with programmatic stream serialization (PDL)
    cudaLaunchConfig_t cfg = {};
    cfg.gridDim  = dim3(N_NODES, 1, 1);
    cfg.blockDim = dim3(256, 1, 1);
    cfg.dynamicSmemBytes = 0;
    cfg.stream = 0;
    cudaLaunchAttribute attrs[1];
    attrs[0].id = cudaLaunchAttributeProgrammaticStreamSerialization;
    attrs[0].val.programmaticStreamSerializationAllowed = 1;
    cfg.attrs = attrs;
    cfg.numAttrs = 1;
    cudaLaunchKernelEx(&cfg, attn_kernel, adj, out);
}